// round 5
// baseline (speedup 1.0000x reference)
#include <cuda_runtime.h>
#include <cstdint>

#define NNODES 50000
#define NEDGES 400000
#define DIM 512
#define NLAYERS 4
#define NGRAPHS 500
#define OUTD 2048          // NLAYERS * DIM
#define EPSF 1e-5f
#define NEG 0.01f

// ---------------- scratch (device globals: no allocation allowed) ----------------
__device__ float g_bufA[(size_t)NNODES * DIM];   // 102.4 MB
__device__ float g_bufB[(size_t)NNODES * DIM];   // 102.4 MB
__device__ int   g_off[NNODES + 1];
__device__ int   g_cur[NNODES];
__device__ int   g_esrc[NEDGES];
__device__ float g_colsum[DIM];
__device__ float g_colsq[DIM];
__device__ float g_scale[DIM];
__device__ float g_shift[DIM];
__device__ int   g_gstart[NGRAPHS + 1];

// ---------------- CSR build ----------------
__global__ void k_zero_cnt() {
    int i = blockIdx.x * blockDim.x + threadIdx.x;
    if (i < NNODES) g_cur[i] = 0;
}

// NOTE: edge_index arrives as int32 (JAX x64 disabled downgrades int64->int32).
__global__ void k_count(const int* __restrict__ ei) {
    int e = blockIdx.x * blockDim.x + threadIdx.x;
    if (e < NEDGES) {
        int d = ei[NEDGES + e];   // dst row
        atomicAdd(&g_cur[d], 1);
    }
}

// single-block exclusive scan of g_cur (counts) -> g_off (offsets), reset cursors
__global__ void k_scan() {
    __shared__ int wsum[32];
    __shared__ int carry_s;
    int tid = threadIdx.x, lane = tid & 31, wid = tid >> 5;
    if (tid == 0) carry_s = 0;
    __syncthreads();
    for (int base = 0; base < NNODES; base += 1024) {
        int i = base + tid;
        int orig = (i < NNODES) ? g_cur[i] : 0;
        int v = orig;
        #pragma unroll
        for (int o = 1; o < 32; o <<= 1) {
            int t = __shfl_up_sync(0xffffffffu, v, o);
            if (lane >= o) v += t;
        }
        if (lane == 31) wsum[wid] = v;
        __syncthreads();
        if (wid == 0) {
            int s = wsum[lane];
            #pragma unroll
            for (int o = 1; o < 32; o <<= 1) {
                int t = __shfl_up_sync(0xffffffffu, s, o);
                if (lane >= o) s += t;
            }
            wsum[lane] = s;
        }
        __syncthreads();
        int prev = (wid > 0) ? wsum[wid - 1] : 0;
        int c = carry_s;
        int incl = c + prev + v;
        int excl = incl - orig;
        if (i < NNODES) { g_off[i] = excl; g_cur[i] = excl; }
        __syncthreads();
        if (tid == 1023) carry_s = incl;
        __syncthreads();
    }
    if (threadIdx.x == 0) g_off[NNODES] = carry_s;
}

__global__ void k_fill(const int* __restrict__ ei) {
    int e = blockIdx.x * blockDim.x + threadIdx.x;
    if (e < NEDGES) {
        int s = ei[e];
        int d = ei[NEDGES + e];
        int p = atomicAdd(&g_cur[d], 1);
        g_esrc[p] = s;
    }
}

// graph start offsets via binary search over sorted batch (int32)
__global__ void k_gstart(const int* __restrict__ batch) {
    int g = blockIdx.x * blockDim.x + threadIdx.x;
    if (g > NGRAPHS) return;
    int lo = 0, hi = NNODES;
    while (lo < hi) {
        int mid = (lo + hi) >> 1;
        if (batch[mid] < g) lo = mid + 1; else hi = mid;
    }
    g_gstart[g] = lo;
}

// ---------------- aggregation: g_bufA[n] = h[n] + sum_{e: dst=n} h[src[e]] ----------------
__global__ void k_aggregate(const float* __restrict__ h, int ldh) {
    int n = blockIdx.x;
    int t = threadIdx.x;   // 128 threads * float4 = 512
    float4 acc = __ldg((const float4*)(h + (size_t)n * ldh) + t);
    int e0 = g_off[n], e1 = g_off[n + 1];
    for (int e = e0; e < e1; ++e) {
        int s = g_esrc[e];
        float4 v = __ldg((const float4*)(h + (size_t)s * ldh) + t);
        acc.x += v.x; acc.y += v.y; acc.z += v.z; acc.w += v.w;
    }
    ((float4*)(g_bufA + (size_t)n * DIM))[t] = acc;
}

// ---------------- fp32 GEMM: C[M,512] = leaky(A[M,512] @ W[512,512] + bias) ----------------
// DIRN=0: A=g_bufA -> C=g_bufB ; DIRN=1: A=g_bufB -> C=g_bufA
// 128x128 blocktile, BK=8, 256 threads, 8x8 per thread, packed fma.rn.f32x2 inner loop.
template <int DIRN>
__global__ void k_gemm(const float* __restrict__ W, const float* __restrict__ bias, int M) {
    const float* A = (DIRN == 0) ? (const float*)g_bufA : (const float*)g_bufB;
    float*       C = (DIRN == 0) ? g_bufB : g_bufA;

    __shared__ __align__(16) float As[8][128];
    __shared__ __align__(16) float Bs[8][128];
    int bm = blockIdx.y * 128;
    int bn = blockIdx.x * 128;
    int tid = threadIdx.x;        // 256
    int tr = tid / 16;            // 0..15
    int tc = tid % 16;            // 0..15
    int arow = tid / 2;           // 0..127
    int acol = (tid % 2) * 4;     // 0 or 4
    int brow = tid / 32;          // 0..7
    int bcol = (tid % 32) * 4;    // 0..124

    unsigned long long acc[8][4] = {};   // 8 rows x 4 f32x2 pairs (= 8 cols)

    for (int k0 = 0; k0 < 512; k0 += 8) {
        float4 av = make_float4(0.f, 0.f, 0.f, 0.f);
        int gr = bm + arow;
        if (gr < M) av = *(const float4*)(A + (size_t)gr * 512 + k0 + acol);
        As[acol + 0][arow] = av.x;
        As[acol + 1][arow] = av.y;
        As[acol + 2][arow] = av.z;
        As[acol + 3][arow] = av.w;
        *(float4*)&Bs[brow][bcol] = *(const float4*)(W + (size_t)(k0 + brow) * 512 + bn + bcol);
        __syncthreads();
        #pragma unroll
        for (int kk = 0; kk < 8; ++kk) {
            float a[8];
            *(float4*)(a)     = *(const float4*)&As[kk][tr * 8];
            *(float4*)(a + 4) = *(const float4*)&As[kk][tr * 8 + 4];
            unsigned long long bp[4];
            #pragma unroll
            for (int jp = 0; jp < 4; ++jp)
                bp[jp] = *(const unsigned long long*)&Bs[kk][tc * 8 + jp * 2];
            #pragma unroll
            for (int i = 0; i < 8; ++i) {
                unsigned long long ap;
                asm("mov.b64 %0, {%1, %1};" : "=l"(ap) : "f"(a[i]));
                #pragma unroll
                for (int jp = 0; jp < 4; ++jp)
                    asm("fma.rn.f32x2 %0, %1, %2, %0;" : "+l"(acc[i][jp]) : "l"(ap), "l"(bp[jp]));
            }
        }
        __syncthreads();
    }

    #pragma unroll
    for (int i = 0; i < 8; ++i) {
        int r = bm + tr * 8 + i;
        if (r >= M) continue;
        #pragma unroll
        for (int jp = 0; jp < 4; ++jp) {
            float lo, hi;
            asm("mov.b64 {%0, %1}, %2;" : "=f"(lo), "=f"(hi) : "l"(acc[i][jp]));
            int c = bn + tc * 8 + jp * 2;
            lo += bias[c];
            hi += bias[c + 1];
            lo = lo >= 0.f ? lo : NEG * lo;
            hi = hi >= 0.f ? hi : NEG * hi;
            float2 o = make_float2(lo, hi);
            *(float2*)(C + (size_t)r * 512 + c) = o;
        }
    }
}

// ---------------- NodeNorm: per-row standardization of g_bufA (in place) ----------------
__global__ void k_nodenorm() {
    int n = blockIdx.x;
    int t = threadIdx.x;   // 128
    float4* row = (float4*)(g_bufA + (size_t)n * DIM);
    float4 v = row[t];
    float s  = v.x + v.y + v.z + v.w;
    float sq = v.x * v.x + v.y * v.y + v.z * v.z + v.w * v.w;
    #pragma unroll
    for (int o = 16; o; o >>= 1) {
        s  += __shfl_down_sync(0xffffffffu, s, o);
        sq += __shfl_down_sync(0xffffffffu, sq, o);
    }
    __shared__ float ssum[4], ssq[4];
    int lane = t & 31, wid = t >> 5;
    if (lane == 0) { ssum[wid] = s; ssq[wid] = sq; }
    __syncthreads();
    float S = ssum[0] + ssum[1] + ssum[2] + ssum[3];
    float Q = ssq[0] + ssq[1] + ssq[2] + ssq[3];
    float mean = S * (1.0f / DIM);
    float var  = Q * (1.0f / DIM) - mean * mean;
    float inv  = rsqrtf(var + EPSF);
    v.x = (v.x - mean) * inv;
    v.y = (v.y - mean) * inv;
    v.z = (v.z - mean) * inv;
    v.w = (v.w - mean) * inv;
    row[t] = v;
}

// ---------------- BatchNorm stats over g_bufA ----------------
__global__ void k_zero512() {
    int t = threadIdx.x;
    g_colsum[t] = 0.f;
    g_colsq[t] = 0.f;
}

__global__ void k_colstats() {
    int c = blockIdx.x * 128 + threadIdx.x;       // blockIdx.x in [0,4)
    const int ROWS_PER = 782;                     // 782 * 64 >= 50000
    int r0 = blockIdx.y * ROWS_PER;
    int r1 = r0 + ROWS_PER; if (r1 > NNODES) r1 = NNODES;
    float s = 0.f, q = 0.f;
    for (int r = r0; r < r1; ++r) {
        float v = g_bufA[(size_t)r * DIM + c];
        s += v; q += v * v;
    }
    atomicAdd(&g_colsum[c], s);
    atomicAdd(&g_colsq[c], q);
}

__global__ void k_bnfinal(const float* __restrict__ gamma, const float* __restrict__ beta) {
    int c = threadIdx.x;  // 512
    float mean = g_colsum[c] * (1.0f / NNODES);
    float var  = g_colsq[c] * (1.0f / NNODES) - mean * mean;
    float inv  = rsqrtf(var + EPSF);
    float sc   = gamma[c] * inv;
    g_scale[c] = sc;
    g_shift[c] = beta[c] - mean * sc;
}

// ---------------- apply BN to g_bufA -> x_local slice ----------------
__global__ void k_apply(float* __restrict__ xlocal, int layer) {
    int idx = blockIdx.x * blockDim.x + threadIdx.x;  // over N*DIM/4
    if (idx >= NNODES * (DIM / 4)) return;
    int n  = idx / (DIM / 4);
    int c4 = idx % (DIM / 4);
    float4 v = ((const float4*)g_bufA)[idx];
    int c = c4 * 4;
    v.x = v.x * g_scale[c + 0] + g_shift[c + 0];
    v.y = v.y * g_scale[c + 1] + g_shift[c + 1];
    v.z = v.z * g_scale[c + 2] + g_shift[c + 2];
    v.w = v.w * g_scale[c + 3] + g_shift[c + 3];
    ((float4*)(xlocal + (size_t)n * OUTD + (size_t)layer * DIM))[c4] = v;
}

// ---------------- global_add_pool over all layers at once ----------------
__global__ void k_pool(const float* __restrict__ xlocal, float* __restrict__ xglobal) {
    int g = blockIdx.x;
    int c = blockIdx.y * 128 + threadIdx.x;   // blockIdx.y in [0,16): 16*128 = 2048
    int r0 = g_gstart[g], r1 = g_gstart[g + 1];
    float s = 0.f;
    for (int r = r0; r < r1; ++r) s += xlocal[(size_t)r * OUTD + c];
    xglobal[(size_t)g * OUTD + c] = s;
}

// ---------------- driver ----------------
extern "C" void kernel_launch(void* const* d_in, const int* in_sizes, int n_in,
                              void* d_out, int out_size) {
    const float* x     = (const float*)d_in[0];
    const int*   ei    = (const int*)d_in[1];      // int32 on the wire (JAX x64 off)
    const int*   batch = (const int*)d_in[2];      // int32 on the wire
    const float* W1    = (const float*)d_in[3];
    const float* b1    = (const float*)d_in[4];
    const float* W2    = (const float*)d_in[5];
    const float* b2    = (const float*)d_in[6];
    const float* gamma = (const float*)d_in[7];
    const float* beta  = (const float*)d_in[8];

    float* out     = (float*)d_out;
    float* xglobal = out;                                  // [500, 2048]
    float* xlocal  = out + (size_t)NGRAPHS * OUTD;         // [50000, 2048]

    // CSR build (same graph reused by all 4 layers)
    k_zero_cnt<<<(NNODES + 255) / 256, 256>>>();
    k_count<<<(NEDGES + 255) / 256, 256>>>(ei);
    k_scan<<<1, 1024>>>();
    k_fill<<<(NEDGES + 255) / 256, 256>>>(ei);
    k_gstart<<<2, 256>>>(batch);

    dim3 gemm_grid(DIM / 128, (NNODES + 127) / 128);

    for (int l = 0; l < NLAYERS; ++l) {
        const float* h = (l == 0) ? x : (xlocal + (size_t)(l - 1) * DIM);
        int ldh = (l == 0) ? DIM : OUTD;
        k_aggregate<<<NNODES, 128>>>(h, ldh);
        k_gemm<0><<<gemm_grid, 256>>>(W1 + (size_t)l * DIM * DIM, b1 + (size_t)l * DIM, NNODES);
        k_gemm<1><<<gemm_grid, 256>>>(W2 + (size_t)l * DIM * DIM, b2 + (size_t)l * DIM, NNODES);
        k_nodenorm<<<NNODES, 128>>>();
        k_zero512<<<1, 512>>>();
        k_colstats<<<dim3(4, 64), 128>>>();
        k_bnfinal<<<1, 512>>>(gamma + (size_t)l * DIM, beta + (size_t)l * DIM);
        k_apply<<<(NNODES * (DIM / 4) + 255) / 256, 256>>>(xlocal, l);
    }

    k_pool<<<dim3(NGRAPHS, 16), 128>>>(xlocal, xglobal);
}

// round 7
// speedup vs baseline: 2.2635x; 2.2635x over previous
#include <cuda_runtime.h>
#include <cuda_bf16.h>
#include <cstdint>

#define NNODES 50000
#define NEDGES 400000
#define DIM 512
#define NLAYERS 4
#define NGRAPHS 500
#define OUTD 2048
#define EPSF 1e-5f
#define NEG 0.01f

// ---------------- scratch ----------------
__device__ float g_bufA[(size_t)NNODES * DIM];
__device__ __nv_bfloat16 g_hi[(size_t)NNODES * DIM];    // GEMM1 input (from aggregate)
__device__ __nv_bfloat16 g_lo[(size_t)NNODES * DIM];
__device__ __nv_bfloat16 g_hi2[(size_t)NNODES * DIM];   // GEMM1 output / GEMM2 input
__device__ __nv_bfloat16 g_lo2[(size_t)NNODES * DIM];
__device__ __nv_bfloat16 g_wt1h[DIM * DIM], g_wt1l[DIM * DIM];
__device__ __nv_bfloat16 g_wt2h[DIM * DIM], g_wt2l[DIM * DIM];
__device__ int   g_off[NNODES + 1];
__device__ int   g_cur[NNODES];
__device__ int   g_esrc[NEDGES];
__device__ float g_colsum[DIM];
__device__ float g_colsq[DIM];
__device__ float g_scale[DIM];
__device__ float g_shift[DIM];
__device__ int   g_gstart[NGRAPHS + 1];

__device__ __forceinline__ uint32_t smem_u32(const void* p) {
    uint32_t a;
    asm("{ .reg .u64 t; cvta.to.shared.u64 t, %1; cvt.u32.u64 %0, t; }" : "=r"(a) : "l"(p));
    return a;
}

#define LDMX4(r0, r1, r2, r3, addr) \
    asm volatile("ldmatrix.sync.aligned.m8n8.x4.shared.b16 {%0,%1,%2,%3}, [%4];" \
        : "=r"(r0), "=r"(r1), "=r"(r2), "=r"(r3) : "r"(addr))

#define MMA16816(d, a0, a1, a2, a3, b0, b1) \
    asm volatile("mma.sync.aligned.m16n8k16.row.col.f32.bf16.bf16.f32 " \
        "{%0,%1,%2,%3}, {%4,%5,%6,%7}, {%8,%9}, {%0,%1,%2,%3};" \
        : "+f"((d)[0]), "+f"((d)[1]), "+f"((d)[2]), "+f"((d)[3]) \
        : "r"(a0), "r"(a1), "r"(a2), "r"(a3), "r"(b0), "r"(b1))

__device__ __forceinline__ __nv_bfloat162 pk2(float a, float b) {
    __nv_bfloat162 r; r.x = __float2bfloat16(a); r.y = __float2bfloat16(b); return r;
}

// ---------------- CSR build ----------------
__global__ void k_zero_cnt() {
    int i = blockIdx.x * blockDim.x + threadIdx.x;
    if (i < NNODES) g_cur[i] = 0;
}
__global__ void k_count(const int* __restrict__ ei) {
    int e = blockIdx.x * blockDim.x + threadIdx.x;
    if (e < NEDGES) atomicAdd(&g_cur[ei[NEDGES + e]], 1);
}
__global__ void k_scan() {
    __shared__ int wsum[32];
    __shared__ int carry_s;
    int tid = threadIdx.x, lane = tid & 31, wid = tid >> 5;
    if (tid == 0) carry_s = 0;
    __syncthreads();
    for (int base = 0; base < NNODES; base += 1024) {
        int i = base + tid;
        int orig = (i < NNODES) ? g_cur[i] : 0;
        int v = orig;
        #pragma unroll
        for (int o = 1; o < 32; o <<= 1) {
            int t = __shfl_up_sync(0xffffffffu, v, o);
            if (lane >= o) v += t;
        }
        if (lane == 31) wsum[wid] = v;
        __syncthreads();
        if (wid == 0) {
            int s = wsum[lane];
            #pragma unroll
            for (int o = 1; o < 32; o <<= 1) {
                int t = __shfl_up_sync(0xffffffffu, s, o);
                if (lane >= o) s += t;
            }
            wsum[lane] = s;
        }
        __syncthreads();
        int prev = (wid > 0) ? wsum[wid - 1] : 0;
        int incl = carry_s + prev + v;
        int excl = incl - orig;
        if (i < NNODES) { g_off[i] = excl; g_cur[i] = excl; }
        __syncthreads();
        if (tid == 1023) carry_s = incl;
        __syncthreads();
    }
    if (threadIdx.x == 0) g_off[NNODES] = carry_s;
}
__global__ void k_fill(const int* __restrict__ ei) {
    int e = blockIdx.x * blockDim.x + threadIdx.x;
    if (e < NEDGES) {
        int p = atomicAdd(&g_cur[ei[NEDGES + e]], 1);
        g_esrc[p] = ei[e];
    }
}
__global__ void k_gstart(const int* __restrict__ batch) {
    int g = blockIdx.x * blockDim.x + threadIdx.x;
    if (g > NGRAPHS) return;
    int lo = 0, hi = NNODES;
    while (lo < hi) {
        int mid = (lo + hi) >> 1;
        if (batch[mid] < g) lo = mid + 1; else hi = mid;
    }
    g_gstart[g] = lo;
}

// ---------------- W transpose + bf16 split: Wt[n][k] = W[k][n] ----------------
template <int WHICH>
__global__ void k_wconv(const float* __restrict__ W) {
    __shared__ float tile[32][33];
    int k0 = blockIdx.y * 32, n0 = blockIdx.x * 32;
    int tx = threadIdx.x, ty = threadIdx.y;
    tile[ty][tx] = W[(size_t)(k0 + ty) * DIM + n0 + tx];
    __syncthreads();
    float v = tile[tx][ty];                 // = W[k0+tx][n0+ty]
    __nv_bfloat16 h = __float2bfloat16(v);
    float lo = v - __bfloat162float(h);
    size_t idx = (size_t)(n0 + ty) * DIM + k0 + tx;
    if (WHICH == 0) { g_wt1h[idx] = h; g_wt1l[idx] = __float2bfloat16(lo); }
    else            { g_wt2h[idx] = h; g_wt2l[idx] = __float2bfloat16(lo); }
}

// ---------------- aggregation -> split bf16 into g_hi/g_lo ----------------
__global__ void k_aggregate(const float* __restrict__ h, int ldh) {
    int n = blockIdx.x;
    int t = threadIdx.x;   // 128 threads * 4 cols
    float4 acc = __ldg((const float4*)(h + (size_t)n * ldh) + t);
    int e0 = g_off[n], e1 = g_off[n + 1];
    for (int e = e0; e < e1; ++e) {
        int s = g_esrc[e];
        float4 v = __ldg((const float4*)(h + (size_t)s * ldh) + t);
        acc.x += v.x; acc.y += v.y; acc.z += v.z; acc.w += v.w;
    }
    __nv_bfloat162 h01 = pk2(acc.x, acc.y), h23 = pk2(acc.z, acc.w);
    float lx = acc.x - __bfloat162float(h01.x);
    float ly = acc.y - __bfloat162float(h01.y);
    float lz = acc.z - __bfloat162float(h23.x);
    float lw = acc.w - __bfloat162float(h23.y);
    __nv_bfloat162* hp = (__nv_bfloat162*)(g_hi + (size_t)n * DIM);
    __nv_bfloat162* lp = (__nv_bfloat162*)(g_lo + (size_t)n * DIM);
    hp[2 * t] = h01; hp[2 * t + 1] = h23;
    lp[2 * t] = pk2(lx, ly); lp[2 * t + 1] = pk2(lz, lw);
}

// ---------------- mma.sync GEMM: leaky(A @ Wt^T + bias), 3-term bf16 split ----------------
// MODE 0: A = g_hi/g_lo, W = Wt1  -> out split bf16 into g_hi2/g_lo2
// MODE 1: A = g_hi2/g_lo2, W = Wt2 -> out fp32 g_bufA
// 128x128 block tile, BK=32, 256 threads (8 warps, 4x2), warp tile 32x64.
template <int MODE>
__global__ void __launch_bounds__(256, 1) k_mma(const float* __restrict__ bias, int M) {
    __shared__ __nv_bfloat16 sAh[128][40];
    __shared__ __nv_bfloat16 sAl[128][40];
    __shared__ __nv_bfloat16 sBh[128][40];
    __shared__ __nv_bfloat16 sBl[128][40];

    const __nv_bfloat16* AH = (MODE == 0) ? g_hi  : g_hi2;
    const __nv_bfloat16* AL = (MODE == 0) ? g_lo  : g_lo2;
    const __nv_bfloat16* WH = (MODE == 0) ? g_wt1h : g_wt2h;
    const __nv_bfloat16* WL = (MODE == 0) ? g_wt1l : g_wt2l;

    int tid  = threadIdx.x;
    int lane = tid & 31;
    int wid  = tid >> 5;
    int wm   = wid & 3;          // 0..3 -> m offset wm*32
    int wn   = wid >> 2;         // 0..1 -> n offset wn*64
    int bm   = blockIdx.y * 128;
    int bn   = blockIdx.x * 128;

    uint32_t uAh = smem_u32(sAh), uAl = smem_u32(sAl);
    uint32_t uBh = smem_u32(sBh), uBl = smem_u32(sBl);

    float acc[2][8][4];
    #pragma unroll
    for (int i = 0; i < 2; ++i)
        #pragma unroll
        for (int j = 0; j < 8; ++j)
            #pragma unroll
            for (int q = 0; q < 4; ++q) acc[i][j][q] = 0.f;

    int lrow = tid >> 1;            // 0..127
    int lseg = (tid & 1) * 2;       // 0 or 2

    // precompute ldmatrix lane addresses (byte offsets within tile, stride 40 bf16 = 80B)
    // A: lanes 0-7: (m+l, k0) ; 8-15: (m+8+l, k0) ; 16-23: (m+l, k0+8) ; 24-31: (m+8+l, k0+8)
    int a_r = (lane & 7) + ((lane >> 3) & 1) * 8;
    int a_c = (lane >> 4) * 8;
    // B: lanes 0-7: (n+l, k0) ; 8-15: (n+l, k0+8) ; 16-23: (n+8+l, k0) ; 24-31: (n+8+l, k0+8)
    int b_r = (lane & 7) + (lane >> 4) * 8;
    int b_c = ((lane >> 3) & 1) * 8;

    for (int kt = 0; kt < 16; ++kt) {
        int k0 = kt * 32;
        // ---- stage tiles ----
        {
            int gr = bm + lrow;
            bool valid = gr < M;
            #pragma unroll
            for (int j = 0; j < 2; ++j) {
                int seg = lseg + j;                     // 0..3
                uint4 vh = make_uint4(0, 0, 0, 0), vl = make_uint4(0, 0, 0, 0);
                if (valid) {
                    size_t gidx = (size_t)gr * DIM + k0 + seg * 8;
                    vh = *(const uint4*)(AH + gidx);
                    vl = *(const uint4*)(AL + gidx);
                }
                *(uint4*)&sAh[lrow][seg * 8] = vh;
                *(uint4*)&sAl[lrow][seg * 8] = vl;
                size_t widx = (size_t)(bn + lrow) * DIM + k0 + seg * 8;
                *(uint4*)&sBh[lrow][seg * 8] = *(const uint4*)(WH + widx);
                *(uint4*)&sBl[lrow][seg * 8] = *(const uint4*)(WL + widx);
            }
        }
        __syncthreads();
        // ---- compute ----
        #pragma unroll
        for (int ks = 0; ks < 2; ++ks) {
            int kcol = ks * 16;
            uint32_t ah[2][4], al[2][4];
            #pragma unroll
            for (int mt = 0; mt < 2; ++mt) {
                int row = wm * 32 + mt * 16 + a_r;
                uint32_t off = (uint32_t)(row * 40 + kcol + a_c) * 2;
                LDMX4(ah[mt][0], ah[mt][1], ah[mt][2], ah[mt][3], uAh + off);
                LDMX4(al[mt][0], al[mt][1], al[mt][2], al[mt][3], uAl + off);
            }
            uint32_t bh[8][2], bl[8][2];
            #pragma unroll
            for (int g = 0; g < 4; ++g) {               // 2 n-tiles per x4
                int row = wn * 64 + g * 16 + b_r;
                uint32_t off = (uint32_t)(row * 40 + kcol + b_c) * 2;
                LDMX4(bh[2 * g][0], bh[2 * g][1], bh[2 * g + 1][0], bh[2 * g + 1][1], uBh + off);
                LDMX4(bl[2 * g][0], bl[2 * g][1], bl[2 * g + 1][0], bl[2 * g + 1][1], uBl + off);
            }
            #pragma unroll
            for (int mt = 0; mt < 2; ++mt)
                #pragma unroll
                for (int nt = 0; nt < 8; ++nt) {
                    MMA16816(acc[mt][nt], ah[mt][0], ah[mt][1], ah[mt][2], ah[mt][3], bh[nt][0], bh[nt][1]);
                    MMA16816(acc[mt][nt], ah[mt][0], ah[mt][1], ah[mt][2], ah[mt][3], bl[nt][0], bl[nt][1]);
                    MMA16816(acc[mt][nt], al[mt][0], al[mt][1], al[mt][2], al[mt][3], bh[nt][0], bh[nt][1]);
                }
        }
        __syncthreads();
    }

    // ---- epilogue ----
    #pragma unroll
    for (int nt = 0; nt < 8; ++nt) {
        int c = bn + wn * 64 + nt * 8 + (lane & 3) * 2;
        float bb0 = bias[c], bb1 = bias[c + 1];
        #pragma unroll
        for (int mt = 0; mt < 2; ++mt) {
            int r0 = bm + wm * 32 + mt * 16 + (lane >> 2);
            #pragma unroll
            for (int half = 0; half < 2; ++half) {
                int r = r0 + half * 8;
                if (r >= M) continue;
                float v0 = acc[mt][nt][2 * half]     + bb0;
                float v1 = acc[mt][nt][2 * half + 1] + bb1;
                v0 = v0 >= 0.f ? v0 : NEG * v0;
                v1 = v1 >= 0.f ? v1 : NEG * v1;
                if (MODE == 0) {
                    __nv_bfloat162 hh = pk2(v0, v1);
                    float l0 = v0 - __bfloat162float(hh.x);
                    float l1 = v1 - __bfloat162float(hh.y);
                    *(__nv_bfloat162*)(g_hi2 + (size_t)r * DIM + c) = hh;
                    *(__nv_bfloat162*)(g_lo2 + (size_t)r * DIM + c) = pk2(l0, l1);
                } else {
                    *(float2*)(g_bufA + (size_t)r * DIM + c) = make_float2(v0, v1);
                }
            }
        }
    }
}

// ---------------- NodeNorm (in place on g_bufA) ----------------
__global__ void k_nodenorm() {
    int n = blockIdx.x;
    int t = threadIdx.x;   // 128
    float4* row = (float4*)(g_bufA + (size_t)n * DIM);
    float4 v = row[t];
    float s  = v.x + v.y + v.z + v.w;
    float sq = v.x * v.x + v.y * v.y + v.z * v.z + v.w * v.w;
    #pragma unroll
    for (int o = 16; o; o >>= 1) {
        s  += __shfl_down_sync(0xffffffffu, s, o);
        sq += __shfl_down_sync(0xffffffffu, sq, o);
    }
    __shared__ float ssum[4], ssq[4];
    int lane = t & 31, wid = t >> 5;
    if (lane == 0) { ssum[wid] = s; ssq[wid] = sq; }
    __syncthreads();
    float S = ssum[0] + ssum[1] + ssum[2] + ssum[3];
    float Q = ssq[0] + ssq[1] + ssq[2] + ssq[3];
    float mean = S * (1.0f / DIM);
    float var  = Q * (1.0f / DIM) - mean * mean;
    float inv  = rsqrtf(var + EPSF);
    v.x = (v.x - mean) * inv;
    v.y = (v.y - mean) * inv;
    v.z = (v.z - mean) * inv;
    v.w = (v.w - mean) * inv;
    row[t] = v;
}

// ---------------- BatchNorm ----------------
__global__ void k_zero512() {
    g_colsum[threadIdx.x] = 0.f;
    g_colsq[threadIdx.x] = 0.f;
}
__global__ void k_colstats() {
    int c = blockIdx.x * 128 + threadIdx.x;
    const int ROWS_PER = 782;
    int r0 = blockIdx.y * ROWS_PER;
    int r1 = r0 + ROWS_PER; if (r1 > NNODES) r1 = NNODES;
    float s = 0.f, q = 0.f;
    for (int r = r0; r < r1; ++r) {
        float v = g_bufA[(size_t)r * DIM + c];
        s += v; q += v * v;
    }
    atomicAdd(&g_colsum[c], s);
    atomicAdd(&g_colsq[c], q);
}
__global__ void k_bnfinal(const float* __restrict__ gamma, const float* __restrict__ beta) {
    int c = threadIdx.x;
    float mean = g_colsum[c] * (1.0f / NNODES);
    float var  = g_colsq[c] * (1.0f / NNODES) - mean * mean;
    float inv  = rsqrtf(var + EPSF);
    float sc   = gamma[c] * inv;
    g_scale[c] = sc;
    g_shift[c] = beta[c] - mean * sc;
}
__global__ void k_apply(float* __restrict__ xlocal, int layer) {
    int idx = blockIdx.x * blockDim.x + threadIdx.x;
    if (idx >= NNODES * (DIM / 4)) return;
    int n  = idx / (DIM / 4);
    int c4 = idx % (DIM / 4);
    float4 v = ((const float4*)g_bufA)[idx];
    int c = c4 * 4;
    v.x = v.x * g_scale[c + 0] + g_shift[c + 0];
    v.y = v.y * g_scale[c + 1] + g_shift[c + 1];
    v.z = v.z * g_scale[c + 2] + g_shift[c + 2];
    v.w = v.w * g_scale[c + 3] + g_shift[c + 3];
    ((float4*)(xlocal + (size_t)n * OUTD + (size_t)layer * DIM))[c4] = v;
}
__global__ void k_pool(const float* __restrict__ xlocal, float* __restrict__ xglobal) {
    int g = blockIdx.x;
    int c = blockIdx.y * 128 + threadIdx.x;
    int r0 = g_gstart[g], r1 = g_gstart[g + 1];
    float s = 0.f;
    for (int r = r0; r < r1; ++r) s += xlocal[(size_t)r * OUTD + c];
    xglobal[(size_t)g * OUTD + c] = s;
}

// ---------------- driver ----------------
extern "C" void kernel_launch(void* const* d_in, const int* in_sizes, int n_in,
                              void* d_out, int out_size) {
    const float* x     = (const float*)d_in[0];
    const int*   ei    = (const int*)d_in[1];
    const int*   batch = (const int*)d_in[2];
    const float* W1    = (const float*)d_in[3];
    const float* b1    = (const float*)d_in[4];
    const float* W2    = (const float*)d_in[5];
    const float* b2    = (const float*)d_in[6];
    const float* gamma = (const float*)d_in[7];
    const float* beta  = (const float*)d_in[8];

    float* out     = (float*)d_out;
    float* xglobal = out;
    float* xlocal  = out + (size_t)NGRAPHS * OUTD;

    k_zero_cnt<<<(NNODES + 255) / 256, 256>>>();
    k_count<<<(NEDGES + 255) / 256, 256>>>(ei);
    k_scan<<<1, 1024>>>();
    k_fill<<<(NEDGES + 255) / 256, 256>>>(ei);
    k_gstart<<<2, 256>>>(batch);

    dim3 wgrid(16, 16), wblk(32, 32);
    dim3 mma_grid(4, (NNODES + 127) / 128);   // (n-blocks, m-blocks)

    for (int l = 0; l < NLAYERS; ++l) {
        const float* h = (l == 0) ? x : (xlocal + (size_t)(l - 1) * DIM);
        int ldh = (l == 0) ? DIM : OUTD;
        k_wconv<0><<<wgrid, wblk>>>(W1 + (size_t)l * DIM * DIM);
        k_wconv<1><<<wgrid, wblk>>>(W2 + (size_t)l * DIM * DIM);
        k_aggregate<<<NNODES, 128>>>(h, ldh);
        k_mma<0><<<mma_grid, 256>>>(b1 + (size_t)l * DIM, NNODES);
        k_mma<1><<<mma_grid, 256>>>(b2 + (size_t)l * DIM, NNODES);
        k_nodenorm<<<NNODES, 128>>>();
        k_zero512<<<1, 512>>>();
        k_colstats<<<dim3(4, 64), 128>>>();
        k_bnfinal<<<1, 512>>>(gamma + (size_t)l * DIM, beta + (size_t)l * DIM);
        k_apply<<<(NNODES * (DIM / 4) + 255) / 256, 256>>>(xlocal, l);
    }

    k_pool<<<dim3(NGRAPHS, 16), 128>>>(xlocal, xglobal);
}

// round 8
// speedup vs baseline: 2.7717x; 1.2246x over previous
#include <cuda_runtime.h>
#include <cuda_bf16.h>
#include <cstdint>

#define NNODES 50000
#define NEDGES 400000
#define DIM 512
#define NLAYERS 4
#define NGRAPHS 500
#define OUTD 2048
#define EPSF 1e-5f
#define NEG 0.01f

// ---------------- scratch ----------------
__device__ float g_bufA[(size_t)NNODES * DIM];
__device__ __nv_bfloat16 g_hi[(size_t)NNODES * DIM];    // GEMM1 input (from aggregate)
__device__ __nv_bfloat16 g_lo[(size_t)NNODES * DIM];
__device__ __nv_bfloat16 g_hi2[(size_t)NNODES * DIM];   // GEMM1 output / GEMM2 input
__device__ __nv_bfloat16 g_lo2[(size_t)NNODES * DIM];
__device__ __nv_bfloat16 g_wt1h[DIM * DIM], g_wt1l[DIM * DIM];
__device__ __nv_bfloat16 g_wt2h[DIM * DIM], g_wt2l[DIM * DIM];
__device__ int   g_off[NNODES + 1];
__device__ int   g_cur[NNODES];
__device__ int   g_esrc[NEDGES];
__device__ float g_colsum[DIM];
__device__ float g_colsq[DIM];
__device__ float g_scale[DIM];
__device__ float g_shift[DIM];
__device__ int   g_gstart[NGRAPHS + 1];

__device__ __forceinline__ uint32_t smem_u32(const void* p) {
    uint32_t a;
    asm("{ .reg .u64 t; cvta.to.shared.u64 t, %1; cvt.u32.u64 %0, t; }" : "=r"(a) : "l"(p));
    return a;
}

#define LDMX4(r0, r1, r2, r3, addr) \
    asm volatile("ldmatrix.sync.aligned.m8n8.x4.shared.b16 {%0,%1,%2,%3}, [%4];" \
        : "=r"(r0), "=r"(r1), "=r"(r2), "=r"(r3) : "r"(addr))

#define MMA16816(d, a0, a1, a2, a3, b0, b1) \
    asm volatile("mma.sync.aligned.m16n8k16.row.col.f32.bf16.bf16.f32 " \
        "{%0,%1,%2,%3}, {%4,%5,%6,%7}, {%8,%9}, {%0,%1,%2,%3};" \
        : "+f"((d)[0]), "+f"((d)[1]), "+f"((d)[2]), "+f"((d)[3]) \
        : "r"(a0), "r"(a1), "r"(a2), "r"(a3), "r"(b0), "r"(b1))

__device__ __forceinline__ void cp16z(uint32_t dst, const void* src, int srcsize) {
    asm volatile("cp.async.cg.shared.global [%0], [%1], 16, %2;" :: "r"(dst), "l"(src), "r"(srcsize));
}
__device__ __forceinline__ void cp16(uint32_t dst, const void* src) {
    asm volatile("cp.async.cg.shared.global [%0], [%1], 16;" :: "r"(dst), "l"(src));
}
#define CP_COMMIT() asm volatile("cp.async.commit_group;")

__device__ __forceinline__ __nv_bfloat162 pk2(float a, float b) {
    __nv_bfloat162 r; r.x = __float2bfloat16(a); r.y = __float2bfloat16(b); return r;
}

// ---------------- CSR build ----------------
__global__ void k_zero_cnt() {
    int i = blockIdx.x * blockDim.x + threadIdx.x;
    if (i < NNODES) g_cur[i] = 0;
}
__global__ void k_count(const int* __restrict__ ei) {
    int e = blockIdx.x * blockDim.x + threadIdx.x;
    if (e < NEDGES) atomicAdd(&g_cur[ei[NEDGES + e]], 1);
}
__global__ void k_scan() {
    __shared__ int wsum[32];
    __shared__ int carry_s;
    int tid = threadIdx.x, lane = tid & 31, wid = tid >> 5;
    if (tid == 0) carry_s = 0;
    __syncthreads();
    for (int base = 0; base < NNODES; base += 1024) {
        int i = base + tid;
        int orig = (i < NNODES) ? g_cur[i] : 0;
        int v = orig;
        #pragma unroll
        for (int o = 1; o < 32; o <<= 1) {
            int t = __shfl_up_sync(0xffffffffu, v, o);
            if (lane >= o) v += t;
        }
        if (lane == 31) wsum[wid] = v;
        __syncthreads();
        if (wid == 0) {
            int s = wsum[lane];
            #pragma unroll
            for (int o = 1; o < 32; o <<= 1) {
                int t = __shfl_up_sync(0xffffffffu, s, o);
                if (lane >= o) s += t;
            }
            wsum[lane] = s;
        }
        __syncthreads();
        int prev = (wid > 0) ? wsum[wid - 1] : 0;
        int incl = carry_s + prev + v;
        int excl = incl - orig;
        if (i < NNODES) { g_off[i] = excl; g_cur[i] = excl; }
        __syncthreads();
        if (tid == 1023) carry_s = incl;
        __syncthreads();
    }
    if (threadIdx.x == 0) g_off[NNODES] = carry_s;
}
__global__ void k_fill(const int* __restrict__ ei) {
    int e = blockIdx.x * blockDim.x + threadIdx.x;
    if (e < NEDGES) {
        int p = atomicAdd(&g_cur[ei[NEDGES + e]], 1);
        g_esrc[p] = ei[e];
    }
}
__global__ void k_gstart(const int* __restrict__ batch) {
    int g = blockIdx.x * blockDim.x + threadIdx.x;
    if (g > NGRAPHS) return;
    int lo = 0, hi = NNODES;
    while (lo < hi) {
        int mid = (lo + hi) >> 1;
        if (batch[mid] < g) lo = mid + 1; else hi = mid;
    }
    g_gstart[g] = lo;
}

// ---------------- W transpose + bf16 split: Wt[n][k] = W[k][n] ----------------
template <int WHICH>
__global__ void k_wconv(const float* __restrict__ W) {
    __shared__ float tile[32][33];
    int k0 = blockIdx.y * 32, n0 = blockIdx.x * 32;
    int tx = threadIdx.x, ty = threadIdx.y;
    tile[ty][tx] = W[(size_t)(k0 + ty) * DIM + n0 + tx];
    __syncthreads();
    float v = tile[tx][ty];                 // = W[k0+tx][n0+ty]
    __nv_bfloat16 h = __float2bfloat16(v);
    float lo = v - __bfloat162float(h);
    size_t idx = (size_t)(n0 + ty) * DIM + k0 + tx;
    if (WHICH == 0) { g_wt1h[idx] = h; g_wt1l[idx] = __float2bfloat16(lo); }
    else            { g_wt2h[idx] = h; g_wt2l[idx] = __float2bfloat16(lo); }
}

// ---------------- aggregation -> split bf16 into g_hi/g_lo ----------------
__global__ void k_aggregate(const float* __restrict__ h, int ldh) {
    int n = blockIdx.x;
    int t = threadIdx.x;   // 128 threads * 4 cols
    float4 acc = __ldg((const float4*)(h + (size_t)n * ldh) + t);
    int e0 = g_off[n], e1 = g_off[n + 1];
    for (int e = e0; e < e1; ++e) {
        int s = g_esrc[e];
        float4 v = __ldg((const float4*)(h + (size_t)s * ldh) + t);
        acc.x += v.x; acc.y += v.y; acc.z += v.z; acc.w += v.w;
    }
    __nv_bfloat162 h01 = pk2(acc.x, acc.y), h23 = pk2(acc.z, acc.w);
    float lx = acc.x - __bfloat162float(h01.x);
    float ly = acc.y - __bfloat162float(h01.y);
    float lz = acc.z - __bfloat162float(h23.x);
    float lw = acc.w - __bfloat162float(h23.y);
    __nv_bfloat162* hp = (__nv_bfloat162*)(g_hi + (size_t)n * DIM);
    __nv_bfloat162* lp = (__nv_bfloat162*)(g_lo + (size_t)n * DIM);
    hp[2 * t] = h01; hp[2 * t + 1] = h23;
    lp[2 * t] = pk2(lx, ly); lp[2 * t + 1] = pk2(lz, lw);
}

// ---------------- mma.sync GEMM, double-buffered cp.async, dependency-broken terms ----
// MODE 0: A = g_hi/g_lo, W = Wt1  -> out split bf16 into g_hi2/g_lo2
// MODE 1: A = g_hi2/g_lo2, W = Wt2 -> out fp32 g_bufA
// 128x128 block tile, BK=32, 256 threads (8 warps 4x2), warp tile 32x64.
// Dynamic smem: 2 stages x 4 tiles(AH,AL,BH,BL) x [128][40] bf16 = 81920 B.
#define TILE_BYTES 10240          // 128*40*2
#define STAGE_BYTES 40960
#define SMEM_TOTAL 81920

template <int MODE>
__global__ void __launch_bounds__(256, 1) k_mma(const float* __restrict__ bias, int M) {
    extern __shared__ char smem[];
    uint32_t sb = smem_u32(smem);

    const __nv_bfloat16* AH = (MODE == 0) ? g_hi  : g_hi2;
    const __nv_bfloat16* AL = (MODE == 0) ? g_lo  : g_lo2;
    const __nv_bfloat16* WH = (MODE == 0) ? g_wt1h : g_wt2h;
    const __nv_bfloat16* WL = (MODE == 0) ? g_wt1l : g_wt2l;

    int tid  = threadIdx.x;
    int lane = tid & 31;
    int wid  = tid >> 5;
    int wm   = wid & 3;
    int wn   = wid >> 2;
    int bm   = blockIdx.y * 128;
    int bn   = blockIdx.x * 128;

    float acc[2][8][4];
    #pragma unroll
    for (int i = 0; i < 2; ++i)
        #pragma unroll
        for (int j = 0; j < 8; ++j)
            #pragma unroll
            for (int q = 0; q < 4; ++q) acc[i][j][q] = 0.f;

    int lrow = tid >> 1;            // 0..127
    int lseg = (tid & 1) * 2;       // 0 or 2

    // ldmatrix lane address components (row stride = 40 bf16 = 80 B)
    int a_r = (lane & 7) + ((lane >> 3) & 1) * 8;
    int a_c = (lane >> 4) * 8;
    int b_r = (lane & 7) + (lane >> 4) * 8;
    int b_c = ((lane >> 3) & 1) * 8;

    int gr = bm + lrow;
    int asz = (gr < M) ? 16 : 0;
    int grc = (gr < M) ? gr : (M - 1);          // clamped addr (zfilled when asz=0)
    int brow = bn + lrow;

    // ---- staging helper ----
    auto stage_load = [&](int kt, int s) {
        int k0 = kt * 32;
        uint32_t base = sb + s * STAGE_BYTES;
        #pragma unroll
        for (int j = 0; j < 2; ++j) {
            int seg = lseg + j;                 // 0..3 (8 bf16 = 16B each)
            uint32_t soff = (uint32_t)(lrow * 40 + seg * 8) * 2;
            size_t gA = (size_t)grc * DIM + k0 + seg * 8;
            cp16z(base + 0 * TILE_BYTES + soff, AH + gA, asz);
            cp16z(base + 1 * TILE_BYTES + soff, AL + gA, asz);
            size_t gB = (size_t)brow * DIM + k0 + seg * 8;
            cp16(base + 2 * TILE_BYTES + soff, WH + gB);
            cp16(base + 3 * TILE_BYTES + soff, WL + gB);
        }
        CP_COMMIT();
    };

    stage_load(0, 0);

    for (int kt = 0; kt < 16; ++kt) {
        int s = kt & 1;
        if (kt + 1 < 16) {
            stage_load(kt + 1, s ^ 1);
            asm volatile("cp.async.wait_group 1;");
        } else {
            asm volatile("cp.async.wait_group 0;");
        }
        __syncthreads();

        uint32_t uAh = sb + s * STAGE_BYTES;
        uint32_t uAl = uAh + TILE_BYTES;
        uint32_t uBh = uAh + 2 * TILE_BYTES;
        uint32_t uBl = uAh + 3 * TILE_BYTES;

        #pragma unroll
        for (int ks = 0; ks < 2; ++ks) {
            int kcol = ks * 16;
            uint32_t ah[2][4], al[2][4];
            #pragma unroll
            for (int mt = 0; mt < 2; ++mt) {
                int row = wm * 32 + mt * 16 + a_r;
                uint32_t off = (uint32_t)(row * 40 + kcol + a_c) * 2;
                LDMX4(ah[mt][0], ah[mt][1], ah[mt][2], ah[mt][3], uAh + off);
                LDMX4(al[mt][0], al[mt][1], al[mt][2], al[mt][3], uAl + off);
            }
            uint32_t bb[8][2];
            #pragma unroll
            for (int g = 0; g < 4; ++g) {
                int row = wn * 64 + g * 16 + b_r;
                uint32_t off = (uint32_t)(row * 40 + kcol + b_c) * 2;
                LDMX4(bb[2 * g][0], bb[2 * g][1], bb[2 * g + 1][0], bb[2 * g + 1][1], uBh + off);
            }
            // term 0: ah * bh  (16 independent MMAs)
            #pragma unroll
            for (int mt = 0; mt < 2; ++mt)
                #pragma unroll
                for (int nt = 0; nt < 8; ++nt)
                    MMA16816(acc[mt][nt], ah[mt][0], ah[mt][1], ah[mt][2], ah[mt][3], bb[nt][0], bb[nt][1]);
            // term 1: al * bh
            #pragma unroll
            for (int mt = 0; mt < 2; ++mt)
                #pragma unroll
                for (int nt = 0; nt < 8; ++nt)
                    MMA16816(acc[mt][nt], al[mt][0], al[mt][1], al[mt][2], al[mt][3], bb[nt][0], bb[nt][1]);
            // reload b as bl, term 2: ah * bl
            #pragma unroll
            for (int g = 0; g < 4; ++g) {
                int row = wn * 64 + g * 16 + b_r;
                uint32_t off = (uint32_t)(row * 40 + kcol + b_c) * 2;
                LDMX4(bb[2 * g][0], bb[2 * g][1], bb[2 * g + 1][0], bb[2 * g + 1][1], uBl + off);
            }
            #pragma unroll
            for (int mt = 0; mt < 2; ++mt)
                #pragma unroll
                for (int nt = 0; nt < 8; ++nt)
                    MMA16816(acc[mt][nt], ah[mt][0], ah[mt][1], ah[mt][2], ah[mt][3], bb[nt][0], bb[nt][1]);
        }
        __syncthreads();
    }

    // ---- epilogue ----
    #pragma unroll
    for (int nt = 0; nt < 8; ++nt) {
        int c = bn + wn * 64 + nt * 8 + (lane & 3) * 2;
        float bb0 = bias[c], bb1 = bias[c + 1];
        #pragma unroll
        for (int mt = 0; mt < 2; ++mt) {
            int r0 = bm + wm * 32 + mt * 16 + (lane >> 2);
            #pragma unroll
            for (int half = 0; half < 2; ++half) {
                int r = r0 + half * 8;
                if (r >= M) continue;
                float v0 = acc[mt][nt][2 * half]     + bb0;
                float v1 = acc[mt][nt][2 * half + 1] + bb1;
                v0 = v0 >= 0.f ? v0 : NEG * v0;
                v1 = v1 >= 0.f ? v1 : NEG * v1;
                if (MODE == 0) {
                    __nv_bfloat162 hh = pk2(v0, v1);
                    float l0 = v0 - __bfloat162float(hh.x);
                    float l1 = v1 - __bfloat162float(hh.y);
                    *(__nv_bfloat162*)(g_hi2 + (size_t)r * DIM + c) = hh;
                    *(__nv_bfloat162*)(g_lo2 + (size_t)r * DIM + c) = pk2(l0, l1);
                } else {
                    *(float2*)(g_bufA + (size_t)r * DIM + c) = make_float2(v0, v1);
                }
            }
        }
    }
}

// ---------------- NodeNorm (in place on g_bufA) ----------------
__global__ void k_nodenorm() {
    int n = blockIdx.x;
    int t = threadIdx.x;   // 128
    float4* row = (float4*)(g_bufA + (size_t)n * DIM);
    float4 v = row[t];
    float s  = v.x + v.y + v.z + v.w;
    float sq = v.x * v.x + v.y * v.y + v.z * v.z + v.w * v.w;
    #pragma unroll
    for (int o = 16; o; o >>= 1) {
        s  += __shfl_down_sync(0xffffffffu, s, o);
        sq += __shfl_down_sync(0xffffffffu, sq, o);
    }
    __shared__ float ssum[4], ssq[4];
    int lane = t & 31, wid = t >> 5;
    if (lane == 0) { ssum[wid] = s; ssq[wid] = sq; }
    __syncthreads();
    float S = ssum[0] + ssum[1] + ssum[2] + ssum[3];
    float Q = ssq[0] + ssq[1] + ssq[2] + ssq[3];
    float mean = S * (1.0f / DIM);
    float var  = Q * (1.0f / DIM) - mean * mean;
    float inv  = rsqrtf(var + EPSF);
    v.x = (v.x - mean) * inv;
    v.y = (v.y - mean) * inv;
    v.z = (v.z - mean) * inv;
    v.w = (v.w - mean) * inv;
    row[t] = v;
}

// ---------------- BatchNorm ----------------
__global__ void k_zero512() {
    g_colsum[threadIdx.x] = 0.f;
    g_colsq[threadIdx.x] = 0.f;
}
__global__ void k_colstats() {
    int c = blockIdx.x * 128 + threadIdx.x;
    const int ROWS_PER = 782;
    int r0 = blockIdx.y * ROWS_PER;
    int r1 = r0 + ROWS_PER; if (r1 > NNODES) r1 = NNODES;
    float s = 0.f, q = 0.f;
    for (int r = r0; r < r1; ++r) {
        float v = g_bufA[(size_t)r * DIM + c];
        s += v; q += v * v;
    }
    atomicAdd(&g_colsum[c], s);
    atomicAdd(&g_colsq[c], q);
}
__global__ void k_bnfinal(const float* __restrict__ gamma, const float* __restrict__ beta) {
    int c = threadIdx.x;
    float mean = g_colsum[c] * (1.0f / NNODES);
    float var  = g_colsq[c] * (1.0f / NNODES) - mean * mean;
    float inv  = rsqrtf(var + EPSF);
    float sc   = gamma[c] * inv;
    g_scale[c] = sc;
    g_shift[c] = beta[c] - mean * sc;
}
__global__ void k_apply(float* __restrict__ xlocal, int layer) {
    int idx = blockIdx.x * blockDim.x + threadIdx.x;
    if (idx >= NNODES * (DIM / 4)) return;
    int n  = idx / (DIM / 4);
    int c4 = idx % (DIM / 4);
    float4 v = ((const float4*)g_bufA)[idx];
    int c = c4 * 4;
    v.x = v.x * g_scale[c + 0] + g_shift[c + 0];
    v.y = v.y * g_scale[c + 1] + g_shift[c + 1];
    v.z = v.z * g_scale[c + 2] + g_shift[c + 2];
    v.w = v.w * g_scale[c + 3] + g_shift[c + 3];
    ((float4*)(xlocal + (size_t)n * OUTD + (size_t)layer * DIM))[c4] = v;
}
__global__ void k_pool(const float* __restrict__ xlocal, float* __restrict__ xglobal) {
    int g = blockIdx.x;
    int c = blockIdx.y * 128 + threadIdx.x;
    int r0 = g_gstart[g], r1 = g_gstart[g + 1];
    float s = 0.f;
    for (int r = r0; r < r1; ++r) s += xlocal[(size_t)r * OUTD + c];
    xglobal[(size_t)g * OUTD + c] = s;
}

// ---------------- driver ----------------
extern "C" void kernel_launch(void* const* d_in, const int* in_sizes, int n_in,
                              void* d_out, int out_size) {
    const float* x     = (const float*)d_in[0];
    const int*   ei    = (const int*)d_in[1];
    const int*   batch = (const int*)d_in[2];
    const float* W1    = (const float*)d_in[3];
    const float* b1    = (const float*)d_in[4];
    const float* W2    = (const float*)d_in[5];
    const float* b2    = (const float*)d_in[6];
    const float* gamma = (const float*)d_in[7];
    const float* beta  = (const float*)d_in[8];

    float* out     = (float*)d_out;
    float* xglobal = out;
    float* xlocal  = out + (size_t)NGRAPHS * OUTD;

    cudaFuncSetAttribute(k_mma<0>, cudaFuncAttributeMaxDynamicSharedMemorySize, SMEM_TOTAL);
    cudaFuncSetAttribute(k_mma<1>, cudaFuncAttributeMaxDynamicSharedMemorySize, SMEM_TOTAL);

    k_zero_cnt<<<(NNODES + 255) / 256, 256>>>();
    k_count<<<(NEDGES + 255) / 256, 256>>>(ei);
    k_scan<<<1, 1024>>>();
    k_fill<<<(NEDGES + 255) / 256, 256>>>(ei);
    k_gstart<<<2, 256>>>(batch);

    dim3 wgrid(16, 16), wblk(32, 32);
    dim3 mma_grid(4, (NNODES + 127) / 128);   // (n-blocks, m-blocks)

    for (int l = 0; l < NLAYERS; ++l) {
        const float* h = (l == 0) ? x : (xlocal + (size_t)(l - 1) * DIM);
        int ldh = (l == 0) ? DIM : OUTD;
        k_wconv<0><<<wgrid, wblk>>>(W1 + (size_t)l * DIM * DIM);
        k_wconv<1><<<wgrid, wblk>>>(W2 + (size_t)l * DIM * DIM);
        k_aggregate<<<NNODES, 128>>>(h, ldh);
        k_mma<0><<<mma_grid, 256, SMEM_TOTAL>>>(b1 + (size_t)l * DIM, NNODES);
        k_mma<1><<<mma_grid, 256, SMEM_TOTAL>>>(b2 + (size_t)l * DIM, NNODES);
        k_nodenorm<<<NNODES, 128>>>();
        k_zero512<<<1, 512>>>();
        k_colstats<<<dim3(4, 64), 128>>>();
        k_bnfinal<<<1, 512>>>(gamma + (size_t)l * DIM, beta + (size_t)l * DIM);
        k_apply<<<(NNODES * (DIM / 4) + 255) / 256, 256>>>(xlocal, l);
    }

    k_pool<<<dim3(NGRAPHS, 16), 128>>>(xlocal, xglobal);
}

// round 9
// speedup vs baseline: 3.1497x; 1.1364x over previous
#include <cuda_runtime.h>
#include <cuda_bf16.h>
#include <cstdint>

#define NNODES 50000
#define NEDGES 400000
#define DIM 512
#define NLAYERS 4
#define NGRAPHS 500
#define OUTD 2048
#define EPSF 1e-5f
#define NEG 0.01f

// ---------------- scratch ----------------
__device__ float g_bufA[(size_t)NNODES * DIM];
__device__ __nv_bfloat16 g_hi[(size_t)NNODES * DIM];    // GEMM1 input (from aggregate)
__device__ __nv_bfloat16 g_lo[(size_t)NNODES * DIM];
__device__ __nv_bfloat16 g_hi2[(size_t)NNODES * DIM];   // GEMM1 output / GEMM2 input
__device__ __nv_bfloat16 g_lo2[(size_t)NNODES * DIM];
__device__ __nv_bfloat16 g_wt1h[DIM * DIM], g_wt1l[DIM * DIM];
__device__ __nv_bfloat16 g_wt2h[DIM * DIM], g_wt2l[DIM * DIM];
__device__ int   g_off[NNODES + 1];
__device__ int   g_cur[NNODES];
__device__ int   g_esrc[NEDGES];
__device__ float g_colsum[DIM];
__device__ float g_colsq[DIM];
__device__ float g_scale[DIM];
__device__ float g_shift[DIM];
__device__ int   g_gstart[NGRAPHS + 1];

__device__ __forceinline__ uint32_t smem_u32(const void* p) {
    uint32_t a;
    asm("{ .reg .u64 t; cvta.to.shared.u64 t, %1; cvt.u32.u64 %0, t; }" : "=r"(a) : "l"(p));
    return a;
}

#define LDMX4(r0, r1, r2, r3, addr) \
    asm volatile("ldmatrix.sync.aligned.m8n8.x4.shared.b16 {%0,%1,%2,%3}, [%4];" \
        : "=r"(r0), "=r"(r1), "=r"(r2), "=r"(r3) : "r"(addr))

#define MMA16816(d, a0, a1, a2, a3, b0, b1) \
    asm volatile("mma.sync.aligned.m16n8k16.row.col.f32.bf16.bf16.f32 " \
        "{%0,%1,%2,%3}, {%4,%5,%6,%7}, {%8,%9}, {%0,%1,%2,%3};" \
        : "+f"((d)[0]), "+f"((d)[1]), "+f"((d)[2]), "+f"((d)[3]) \
        : "r"(a0), "r"(a1), "r"(a2), "r"(a3), "r"(b0), "r"(b1))

__device__ __forceinline__ void cp16z(uint32_t dst, const void* src, int srcsize) {
    asm volatile("cp.async.cg.shared.global [%0], [%1], 16, %2;" :: "r"(dst), "l"(src), "r"(srcsize));
}
__device__ __forceinline__ void cp16(uint32_t dst, const void* src) {
    asm volatile("cp.async.cg.shared.global [%0], [%1], 16;" :: "r"(dst), "l"(src));
}
#define CP_COMMIT() asm volatile("cp.async.commit_group;")

__device__ __forceinline__ __nv_bfloat162 pk2(float a, float b) {
    __nv_bfloat162 r; r.x = __float2bfloat16(a); r.y = __float2bfloat16(b); return r;
}

// ---------------- CSR build ----------------
__global__ void k_zero_cnt() {
    int i = blockIdx.x * blockDim.x + threadIdx.x;
    if (i < NNODES) g_cur[i] = 0;
}
__global__ void k_count(const int* __restrict__ ei) {
    int e = blockIdx.x * blockDim.x + threadIdx.x;
    if (e < NEDGES) atomicAdd(&g_cur[ei[NEDGES + e]], 1);
}
__global__ void k_scan() {
    __shared__ int wsum[32];
    __shared__ int carry_s;
    int tid = threadIdx.x, lane = tid & 31, wid = tid >> 5;
    if (tid == 0) carry_s = 0;
    __syncthreads();
    for (int base = 0; base < NNODES; base += 1024) {
        int i = base + tid;
        int orig = (i < NNODES) ? g_cur[i] : 0;
        int v = orig;
        #pragma unroll
        for (int o = 1; o < 32; o <<= 1) {
            int t = __shfl_up_sync(0xffffffffu, v, o);
            if (lane >= o) v += t;
        }
        if (lane == 31) wsum[wid] = v;
        __syncthreads();
        if (wid == 0) {
            int s = wsum[lane];
            #pragma unroll
            for (int o = 1; o < 32; o <<= 1) {
                int t = __shfl_up_sync(0xffffffffu, s, o);
                if (lane >= o) s += t;
            }
            wsum[lane] = s;
        }
        __syncthreads();
        int prev = (wid > 0) ? wsum[wid - 1] : 0;
        int incl = carry_s + prev + v;
        int excl = incl - orig;
        if (i < NNODES) { g_off[i] = excl; g_cur[i] = excl; }
        __syncthreads();
        if (tid == 1023) carry_s = incl;
        __syncthreads();
    }
    if (threadIdx.x == 0) g_off[NNODES] = carry_s;
}
__global__ void k_fill(const int* __restrict__ ei) {
    int e = blockIdx.x * blockDim.x + threadIdx.x;
    if (e < NEDGES) {
        int p = atomicAdd(&g_cur[ei[NEDGES + e]], 1);
        g_esrc[p] = ei[e];
    }
}
__global__ void k_gstart(const int* __restrict__ batch) {
    int g = blockIdx.x * blockDim.x + threadIdx.x;
    if (g > NGRAPHS) return;
    int lo = 0, hi = NNODES;
    while (lo < hi) {
        int mid = (lo + hi) >> 1;
        if (batch[mid] < g) lo = mid + 1; else hi = mid;
    }
    g_gstart[g] = lo;
}

// ---------------- W transpose + bf16 split: Wt[n][k] = W[k][n] ----------------
template <int WHICH>
__global__ void k_wconv(const float* __restrict__ W) {
    __shared__ float tile[32][33];
    int k0 = blockIdx.y * 32, n0 = blockIdx.x * 32;
    int tx = threadIdx.x, ty = threadIdx.y;
    tile[ty][tx] = W[(size_t)(k0 + ty) * DIM + n0 + tx];
    __syncthreads();
    float v = tile[tx][ty];                 // = W[k0+tx][n0+ty]
    __nv_bfloat16 h = __float2bfloat16(v);
    float lo = v - __bfloat162float(h);
    size_t idx = (size_t)(n0 + ty) * DIM + k0 + tx;
    if (WHICH == 0) { g_wt1h[idx] = h; g_wt1l[idx] = __float2bfloat16(lo); }
    else            { g_wt2h[idx] = h; g_wt2l[idx] = __float2bfloat16(lo); }
}

// ---------------- aggregation -> split bf16 into g_hi/g_lo ----------------
__global__ void k_aggregate(const float* __restrict__ h, int ldh) {
    int n = blockIdx.x;
    int t = threadIdx.x;   // 128 threads * 4 cols
    float4 acc = __ldg((const float4*)(h + (size_t)n * ldh) + t);
    int e0 = g_off[n], e1 = g_off[n + 1];
    for (int e = e0; e < e1; ++e) {
        int s = g_esrc[e];
        float4 v = __ldg((const float4*)(h + (size_t)s * ldh) + t);
        acc.x += v.x; acc.y += v.y; acc.z += v.z; acc.w += v.w;
    }
    __nv_bfloat162 h01 = pk2(acc.x, acc.y), h23 = pk2(acc.z, acc.w);
    float lx = acc.x - __bfloat162float(h01.x);
    float ly = acc.y - __bfloat162float(h01.y);
    float lz = acc.z - __bfloat162float(h23.x);
    float lw = acc.w - __bfloat162float(h23.y);
    __nv_bfloat162* hp = (__nv_bfloat162*)(g_hi + (size_t)n * DIM);
    __nv_bfloat162* lp = (__nv_bfloat162*)(g_lo + (size_t)n * DIM);
    hp[2 * t] = h01; hp[2 * t + 1] = h23;
    lp[2 * t] = pk2(lx, ly); lp[2 * t + 1] = pk2(lz, lw);
}

// ---------------- mma.sync GEMM, double-buffered cp.async, 2 CTAs/SM ----------------
// MODE 0: A = g_hi/g_lo, W = Wt1  -> out split bf16 into g_hi2/g_lo2
// MODE 1: A = g_hi2/g_lo2, W = Wt2 -> out fp32 g_bufA
// 128x128 block tile, BK=32, 256 threads (8 warps 4x2), warp tile 32x64.
// Dynamic smem: 2 stages x 4 tiles(AH,AL,BH,BL) x [128][40] bf16 = 81920 B.
#define TILE_BYTES 10240          // 128*40*2
#define STAGE_BYTES 40960
#define SMEM_TOTAL 81920

template <int MODE>
__global__ void __launch_bounds__(256, 2) k_mma(const float* __restrict__ bias, int M) {
    extern __shared__ char smem[];
    uint32_t sb = smem_u32(smem);

    const __nv_bfloat16* AH = (MODE == 0) ? g_hi  : g_hi2;
    const __nv_bfloat16* AL = (MODE == 0) ? g_lo  : g_lo2;
    const __nv_bfloat16* WH = (MODE == 0) ? g_wt1h : g_wt2h;
    const __nv_bfloat16* WL = (MODE == 0) ? g_wt1l : g_wt2l;

    int tid  = threadIdx.x;
    int lane = tid & 31;
    int wid  = tid >> 5;
    int wm   = wid & 3;
    int wn   = wid >> 2;
    int bm   = blockIdx.y * 128;
    int bn   = blockIdx.x * 128;

    float acc[2][8][4];
    #pragma unroll
    for (int i = 0; i < 2; ++i)
        #pragma unroll
        for (int j = 0; j < 8; ++j)
            #pragma unroll
            for (int q = 0; q < 4; ++q) acc[i][j][q] = 0.f;

    int lrow = tid >> 1;            // 0..127
    int lseg = (tid & 1) * 2;       // 0 or 2

    // ldmatrix lane address components (row stride = 40 bf16 = 80 B)
    int a_r = (lane & 7) + ((lane >> 3) & 1) * 8;
    int a_c = (lane >> 4) * 8;
    int b_r = (lane & 7) + (lane >> 4) * 8;
    int b_c = ((lane >> 3) & 1) * 8;

    int gr = bm + lrow;
    int asz = (gr < M) ? 16 : 0;
    int grc = (gr < M) ? gr : (M - 1);          // clamped addr (zfilled when asz=0)
    int brow = bn + lrow;

    // ---- staging helper ----
    auto stage_load = [&](int kt, int s) {
        int k0 = kt * 32;
        uint32_t base = sb + s * STAGE_BYTES;
        #pragma unroll
        for (int j = 0; j < 2; ++j) {
            int seg = lseg + j;                 // 0..3 (8 bf16 = 16B each)
            uint32_t soff = (uint32_t)(lrow * 40 + seg * 8) * 2;
            size_t gA = (size_t)grc * DIM + k0 + seg * 8;
            cp16z(base + 0 * TILE_BYTES + soff, AH + gA, asz);
            cp16z(base + 1 * TILE_BYTES + soff, AL + gA, asz);
            size_t gB = (size_t)brow * DIM + k0 + seg * 8;
            cp16(base + 2 * TILE_BYTES + soff, WH + gB);
            cp16(base + 3 * TILE_BYTES + soff, WL + gB);
        }
        CP_COMMIT();
    };

    stage_load(0, 0);

    for (int kt = 0; kt < 16; ++kt) {
        int s = kt & 1;
        if (kt + 1 < 16) {
            stage_load(kt + 1, s ^ 1);
            asm volatile("cp.async.wait_group 1;");
        } else {
            asm volatile("cp.async.wait_group 0;");
        }
        __syncthreads();

        uint32_t uAh = sb + s * STAGE_BYTES;
        uint32_t uAl = uAh + TILE_BYTES;
        uint32_t uBh = uAh + 2 * TILE_BYTES;
        uint32_t uBl = uAh + 3 * TILE_BYTES;

        #pragma unroll
        for (int ks = 0; ks < 2; ++ks) {
            int kcol = ks * 16;
            uint32_t ah[2][4], al[2][4];
            #pragma unroll
            for (int mt = 0; mt < 2; ++mt) {
                int row = wm * 32 + mt * 16 + a_r;
                uint32_t off = (uint32_t)(row * 40 + kcol + a_c) * 2;
                LDMX4(ah[mt][0], ah[mt][1], ah[mt][2], ah[mt][3], uAh + off);
                LDMX4(al[mt][0], al[mt][1], al[mt][2], al[mt][3], uAl + off);
            }
            uint32_t bb[8][2];
            #pragma unroll
            for (int g = 0; g < 4; ++g) {
                int row = wn * 64 + g * 16 + b_r;
                uint32_t off = (uint32_t)(row * 40 + kcol + b_c) * 2;
                LDMX4(bb[2 * g][0], bb[2 * g][1], bb[2 * g + 1][0], bb[2 * g + 1][1], uBh + off);
            }
            // term 0: ah * bh  (16 independent MMAs)
            #pragma unroll
            for (int mt = 0; mt < 2; ++mt)
                #pragma unroll
                for (int nt = 0; nt < 8; ++nt)
                    MMA16816(acc[mt][nt], ah[mt][0], ah[mt][1], ah[mt][2], ah[mt][3], bb[nt][0], bb[nt][1]);
            // term 1: al * bh
            #pragma unroll
            for (int mt = 0; mt < 2; ++mt)
                #pragma unroll
                for (int nt = 0; nt < 8; ++nt)
                    MMA16816(acc[mt][nt], al[mt][0], al[mt][1], al[mt][2], al[mt][3], bb[nt][0], bb[nt][1]);
            // reload b as bl, term 2: ah * bl
            #pragma unroll
            for (int g = 0; g < 4; ++g) {
                int row = wn * 64 + g * 16 + b_r;
                uint32_t off = (uint32_t)(row * 40 + kcol + b_c) * 2;
                LDMX4(bb[2 * g][0], bb[2 * g][1], bb[2 * g + 1][0], bb[2 * g + 1][1], uBl + off);
            }
            #pragma unroll
            for (int mt = 0; mt < 2; ++mt)
                #pragma unroll
                for (int nt = 0; nt < 8; ++nt)
                    MMA16816(acc[mt][nt], ah[mt][0], ah[mt][1], ah[mt][2], ah[mt][3], bb[nt][0], bb[nt][1]);
        }
        __syncthreads();
    }

    // ---- epilogue ----
    #pragma unroll
    for (int nt = 0; nt < 8; ++nt) {
        int c = bn + wn * 64 + nt * 8 + (lane & 3) * 2;
        float bb0 = bias[c], bb1 = bias[c + 1];
        #pragma unroll
        for (int mt = 0; mt < 2; ++mt) {
            int r0 = bm + wm * 32 + mt * 16 + (lane >> 2);
            #pragma unroll
            for (int half = 0; half < 2; ++half) {
                int r = r0 + half * 8;
                if (r >= M) continue;
                float v0 = acc[mt][nt][2 * half]     + bb0;
                float v1 = acc[mt][nt][2 * half + 1] + bb1;
                v0 = v0 >= 0.f ? v0 : NEG * v0;
                v1 = v1 >= 0.f ? v1 : NEG * v1;
                if (MODE == 0) {
                    __nv_bfloat162 hh = pk2(v0, v1);
                    float l0 = v0 - __bfloat162float(hh.x);
                    float l1 = v1 - __bfloat162float(hh.y);
                    *(__nv_bfloat162*)(g_hi2 + (size_t)r * DIM + c) = hh;
                    *(__nv_bfloat162*)(g_lo2 + (size_t)r * DIM + c) = pk2(l0, l1);
                } else {
                    *(float2*)(g_bufA + (size_t)r * DIM + c) = make_float2(v0, v1);
                }
            }
        }
    }
}

// ---------------- NodeNorm (in place on g_bufA) ----------------
__global__ void k_nodenorm() {
    int n = blockIdx.x;
    int t = threadIdx.x;   // 128
    float4* row = (float4*)(g_bufA + (size_t)n * DIM);
    float4 v = row[t];
    float s  = v.x + v.y + v.z + v.w;
    float sq = v.x * v.x + v.y * v.y + v.z * v.z + v.w * v.w;
    #pragma unroll
    for (int o = 16; o; o >>= 1) {
        s  += __shfl_down_sync(0xffffffffu, s, o);
        sq += __shfl_down_sync(0xffffffffu, sq, o);
    }
    __shared__ float ssum[4], ssq[4];
    int lane = t & 31, wid = t >> 5;
    if (lane == 0) { ssum[wid] = s; ssq[wid] = sq; }
    __syncthreads();
    float S = ssum[0] + ssum[1] + ssum[2] + ssum[3];
    float Q = ssq[0] + ssq[1] + ssq[2] + ssq[3];
    float mean = S * (1.0f / DIM);
    float var  = Q * (1.0f / DIM) - mean * mean;
    float inv  = rsqrtf(var + EPSF);
    v.x = (v.x - mean) * inv;
    v.y = (v.y - mean) * inv;
    v.z = (v.z - mean) * inv;
    v.w = (v.w - mean) * inv;
    row[t] = v;
}

// ---------------- BatchNorm ----------------
__global__ void k_zero512() {
    g_colsum[threadIdx.x] = 0.f;
    g_colsq[threadIdx.x] = 0.f;
}
__global__ void k_colstats() {
    int c = blockIdx.x * 128 + threadIdx.x;
    const int ROWS_PER = 782;
    int r0 = blockIdx.y * ROWS_PER;
    int r1 = r0 + ROWS_PER; if (r1 > NNODES) r1 = NNODES;
    float s = 0.f, q = 0.f;
    for (int r = r0; r < r1; ++r) {
        float v = g_bufA[(size_t)r * DIM + c];
        s += v; q += v * v;
    }
    atomicAdd(&g_colsum[c], s);
    atomicAdd(&g_colsq[c], q);
}
__global__ void k_bnfinal(const float* __restrict__ gamma, const float* __restrict__ beta) {
    int c = threadIdx.x;
    float mean = g_colsum[c] * (1.0f / NNODES);
    float var  = g_colsq[c] * (1.0f / NNODES) - mean * mean;
    float inv  = rsqrtf(var + EPSF);
    float sc   = gamma[c] * inv;
    g_scale[c] = sc;
    g_shift[c] = beta[c] - mean * sc;
}
__global__ void k_apply(float* __restrict__ xlocal, int layer) {
    int idx = blockIdx.x * blockDim.x + threadIdx.x;
    if (idx >= NNODES * (DIM / 4)) return;
    int n  = idx / (DIM / 4);
    int c4 = idx % (DIM / 4);
    float4 v = ((const float4*)g_bufA)[idx];
    int c = c4 * 4;
    v.x = v.x * g_scale[c + 0] + g_shift[c + 0];
    v.y = v.y * g_scale[c + 1] + g_shift[c + 1];
    v.z = v.z * g_scale[c + 2] + g_shift[c + 2];
    v.w = v.w * g_scale[c + 3] + g_shift[c + 3];
    ((float4*)(xlocal + (size_t)n * OUTD + (size_t)layer * DIM))[c4] = v;
}
__global__ void k_pool(const float* __restrict__ xlocal, float* __restrict__ xglobal) {
    int g = blockIdx.x;
    int c = blockIdx.y * 128 + threadIdx.x;
    int r0 = g_gstart[g], r1 = g_gstart[g + 1];
    float s = 0.f;
    for (int r = r0; r < r1; ++r) s += xlocal[(size_t)r * OUTD + c];
    xglobal[(size_t)g * OUTD + c] = s;
}

// ---------------- driver ----------------
extern "C" void kernel_launch(void* const* d_in, const int* in_sizes, int n_in,
                              void* d_out, int out_size) {
    const float* x     = (const float*)d_in[0];
    const int*   ei    = (const int*)d_in[1];
    const int*   batch = (const int*)d_in[2];
    const float* W1    = (const float*)d_in[3];
    const float* b1    = (const float*)d_in[4];
    const float* W2    = (const float*)d_in[5];
    const float* b2    = (const float*)d_in[6];
    const float* gamma = (const float*)d_in[7];
    const float* beta  = (const float*)d_in[8];

    float* out     = (float*)d_out;
    float* xglobal = out;
    float* xlocal  = out + (size_t)NGRAPHS * OUTD;

    cudaFuncSetAttribute(k_mma<0>, cudaFuncAttributeMaxDynamicSharedMemorySize, SMEM_TOTAL);
    cudaFuncSetAttribute(k_mma<1>, cudaFuncAttributeMaxDynamicSharedMemorySize, SMEM_TOTAL);

    k_zero_cnt<<<(NNODES + 255) / 256, 256>>>();
    k_count<<<(NEDGES + 255) / 256, 256>>>(ei);
    k_scan<<<1, 1024>>>();
    k_fill<<<(NEDGES + 255) / 256, 256>>>(ei);
    k_gstart<<<2, 256>>>(batch);

    dim3 wgrid(16, 16), wblk(32, 32);
    dim3 mma_grid(4, (NNODES + 127) / 128);   // (n-blocks, m-blocks)

    for (int l = 0; l < NLAYERS; ++l) {
        const float* h = (l == 0) ? x : (xlocal + (size_t)(l - 1) * DIM);
        int ldh = (l == 0) ? DIM : OUTD;
        k_wconv<0><<<wgrid, wblk>>>(W1 + (size_t)l * DIM * DIM);
        k_wconv<1><<<wgrid, wblk>>>(W2 + (size_t)l * DIM * DIM);
        k_aggregate<<<NNODES, 128>>>(h, ldh);
        k_mma<0><<<mma_grid, 256, SMEM_TOTAL>>>(b1 + (size_t)l * DIM, NNODES);
        k_mma<1><<<mma_grid, 256, SMEM_TOTAL>>>(b2 + (size_t)l * DIM, NNODES);
        k_nodenorm<<<NNODES, 128>>>();
        k_zero512<<<1, 512>>>();
        k_colstats<<<dim3(4, 64), 128>>>();
        k_bnfinal<<<1, 512>>>(gamma + (size_t)l * DIM, beta + (size_t)l * DIM);
        k_apply<<<(NNODES * (DIM / 4) + 255) / 256, 256>>>(xlocal, l);
    }

    k_pool<<<dim3(NGRAPHS, 16), 128>>>(xlocal, xglobal);
}